// round 15
// baseline (speedup 1.0000x reference)
#include <cuda_runtime.h>
#include <cuda_bf16.h>
#include <cstdint>

#define N_VAR 4194304
#define M_CHK 2097152
#define DC 10
#define CBLK 64
#define ADJ_BYTES (CBLK * DC * 4)

// scratch (device globals: allocation-free)
__device__ float g_b0[N_VAR];
__device__ float g_b1[N_VAR];
__device__ float g_b2[N_VAR];

__device__ __forceinline__ uint32_t smem_u32(const void* p) {
    uint32_t a;
    asm("{ .reg .u64 t; cvta.to.shared.u64 t, %1; cvt.u32.u64 %0, t; }" : "=r"(a) : "l"(p));
    return a;
}
__device__ __forceinline__ void pdl_trigger() {
    asm volatile("griddepcontrol.launch_dependents;");
}
__device__ __forceinline__ void pdl_wait() {
    asm volatile("griddepcontrol.wait;" ::: "memory");
}

// zero the first accumulator (kernel, not memset, so the PDL chain is unbroken)
__global__ void __launch_bounds__(512) bp_zero(float* __restrict__ acc) {
    pdl_trigger();
    int i = blockIdx.x * 512 + threadIdx.x;
    reinterpret_cast<float4*>(acc)[i] = make_float4(0.f, 0.f, 0.f, 0.f);
}

// seed accumulator: acc = scale*llr0 - v2c_prev  (scale = 1 mid, 2 for final/out)
__global__ void __launch_bounds__(512) bp_seed(const float* __restrict__ llr0,
                                               const float* __restrict__ v2c_prev,
                                               float* __restrict__ acc, float scale) {
    int i = blockIdx.x * 512 + threadIdx.x;
    pdl_trigger();
    pdl_wait();   // v2c_prev produced by the preceding check kernel
    float4 l = __ldg(&reinterpret_cast<const float4*>(llr0)[i]);
    float4 p = __ldg(&reinterpret_cast<const float4*>(v2c_prev)[i]);
    float4 s = make_float4(fmaf(scale, l.x, -p.x), fmaf(scale, l.y, -p.y),
                           fmaf(scale, l.z, -p.z), fmaf(scale, l.w, -p.w));
    reinterpret_cast<float4*>(acc)[i] = s;
}

// check-node update: gather src (L2-only), min-sum, scatter-add into pre-seeded
// dst. Entire prologue (mbarrier init, TMA adj fetch + wait, smem index loads)
// runs BEFORE pdl_wait; only the src gathers / dst atomics are gated.
__global__ void __launch_bounds__(CBLK) bp_check(const int* __restrict__ adj,
                                                 const float* __restrict__ gamma_p,
                                                 const float* __restrict__ src,
                                                 float* __restrict__ dst) {
    __shared__ __align__(16) int s_adj[CBLK * DC];
    __shared__ __align__(8) unsigned long long s_mbar;

    const int tid = threadIdx.x;
    uint32_t mbar = smem_u32(&s_mbar);
    uint32_t sdst = smem_u32(s_adj);

    if (tid == 0) {
        asm volatile("mbarrier.init.shared.b64 [%0], 1;" :: "r"(mbar) : "memory");
    }
    __syncthreads();
    if (tid == 0) {
        asm volatile("mbarrier.arrive.expect_tx.shared.b64 _, [%0], %1;"
                     :: "r"(mbar), "r"((uint32_t)ADJ_BYTES) : "memory");
        const int* gsrc = adj + (size_t)blockIdx.x * (CBLK * DC);
        asm volatile(
            "cp.async.bulk.shared::cta.global.mbarrier::complete_tx::bytes "
            "[%0], [%1], %2, [%3];"
            :: "r"(sdst), "l"(gsrc), "r"((uint32_t)ADJ_BYTES), "r"(mbar) : "memory");
    }
    pdl_trigger();
    const float gamma = __ldg(gamma_p);   // kernel input, safe pre-wait

    // wait for TMA completion (phase 0) — input-only dependency, pre-wait
    {
        uint32_t done;
        asm volatile(
            "{\n\t.reg .pred p;\n\t"
            "mbarrier.try_wait.parity.acquire.cta.shared::cta.b64 p, [%1], 0;\n\t"
            "selp.b32 %0, 1, 0, p;\n\t}"
            : "=r"(done) : "r"(mbar) : "memory");
        while (!done) {
            asm volatile(
                "{\n\t.reg .pred p;\n\t"
                "mbarrier.try_wait.parity.acquire.cta.shared::cta.b64 p, [%1], 0, 0x989680;\n\t"
                "selp.b32 %0, 1, 0, p;\n\t}"
                : "=r"(done) : "r"(mbar) : "memory");
        }
    }

    int idx[DC];
    #pragma unroll
    for (int j = 0; j < DC; j++) idx[j] = s_adj[tid * DC + j];

    pdl_wait();   // src and seeded dst produced by the predecessor
    const float vlast = __ldg(&src[N_VAR - 1]);  // all padded (-1) slots wrap here

    float mag = __int_as_float(0x7f800000);  // +inf
    unsigned sgn = 0u;
    #pragma unroll
    for (int j = 0; j < DC; j++) {
        float v = (idx[j] >= 0) ? __ldcg(&src[idx[j]]) : vlast;
        sgn ^= (__float_as_uint(v + 1e-12f) & 0x80000000u);
        mag = fminf(mag, fabsf(v));
    }
    float c2v = __uint_as_float(__float_as_uint(gamma * mag) ^ sgn);

    #pragma unroll
    for (int j = 0; j < DC; j++) {
        if (idx[j] >= 0) atomicAdd(&dst[idx[j]], c2v);
    }
}

template <typename... Args>
static void launch_pdl(void (*kern)(Args...), int grid, int block, Args... args) {
    cudaLaunchConfig_t cfg = {};
    cfg.gridDim = dim3(grid);
    cfg.blockDim = dim3(block);
    cfg.stream = 0;
    cudaLaunchAttribute attr[1];
    attr[0].id = cudaLaunchAttributeProgrammaticStreamSerialization;
    attr[0].val.programmaticStreamSerializationAllowed = 1;
    cfg.attrs = attr;
    cfg.numAttrs = 1;
    cudaLaunchKernelEx(&cfg, kern, args...);
}

extern "C" void kernel_launch(void* const* d_in, const int* in_sizes, int n_in,
                              void* d_out, int out_size) {
    const float* llr0  = (const float*)d_in[0];
    const float* gamma = (const float*)d_in[1];
    const int*   adj   = (const int*)d_in[2];
    float* out = (float*)d_out;

    float *b0, *b1, *b2;
    cudaGetSymbolAddress((void**)&b0, g_b0);
    cudaGetSymbolAddress((void**)&b1, g_b1);
    cudaGetSymbolAddress((void**)&b2, g_b2);

    const int seed_blocks = N_VAR / 4 / 512;   // 2048
    const int chk_blocks = M_CHK / CBLK;       // 32768

    // n_iter = 5. Iter 1 is exact identity (v2c1 = llr0). Remaining 4 rounds:
    // accumulators pre-seeded with (llr0 - v2c_prev) so check's atomics produce
    // v2c_next in place; final accumulator is d_out seeded with (2*llr0 - v2c_4).
    // All launches use PDL; each kernel's input-only prologue overlaps the
    // predecessor's tail wave.
    launch_pdl(bp_zero, seed_blocks, 512, b0);                       // b0 = 0
    launch_pdl(bp_check, chk_blocks, CBLK, adj, gamma, llr0, b0);    // b0 = v2c_2
    launch_pdl(bp_seed, seed_blocks, 512, llr0, (const float*)b0, b1, 1.f); // b1 = llr0 - v2c_2
    launch_pdl(bp_check, chk_blocks, CBLK, adj, gamma, (const float*)b0, b1); // b1 = v2c_3
    launch_pdl(bp_seed, seed_blocks, 512, llr0, (const float*)b1, b2, 1.f); // b2 = llr0 - v2c_3
    launch_pdl(bp_check, chk_blocks, CBLK, adj, gamma, (const float*)b1, b2); // b2 = v2c_4
    launch_pdl(bp_seed, seed_blocks, 512, llr0, (const float*)b2, out, 2.f); // out = 2*llr0 - v2c_4
    launch_pdl(bp_check, chk_blocks, CBLK, adj, gamma, (const float*)b2, out); // out = llr0 + v2c_5
}

// round 16
// speedup vs baseline: 1.0021x; 1.0021x over previous
#include <cuda_runtime.h>
#include <cuda_bf16.h>
#include <cstdint>

#define N_VAR 4194304
#define M_CHK 2097152
#define DC 10
#define CBLK 128
#define ADJ_BYTES (CBLK * DC * 4)

// scratch (device globals: allocation-free)
__device__ float g_b0[N_VAR];
__device__ float g_b1[N_VAR];
__device__ float g_b2[N_VAR];

__device__ __forceinline__ uint32_t smem_u32(const void* p) {
    uint32_t a;
    asm("{ .reg .u64 t; cvta.to.shared.u64 t, %1; cvt.u32.u64 %0, t; }" : "=r"(a) : "l"(p));
    return a;
}
__device__ __forceinline__ void pdl_trigger() {
    asm volatile("griddepcontrol.launch_dependents;");
}
__device__ __forceinline__ void pdl_wait() {
    asm volatile("griddepcontrol.wait;" ::: "memory");
}

// zero the first accumulator (kernel, not memset, so the PDL chain is unbroken)
__global__ void __launch_bounds__(512) bp_zero(float* __restrict__ acc) {
    pdl_trigger();
    int i = blockIdx.x * 512 + threadIdx.x;
    reinterpret_cast<float4*>(acc)[i] = make_float4(0.f, 0.f, 0.f, 0.f);
}

// seed accumulator: acc = scale*llr0 - v2c_prev  (scale = 1 mid, 2 for final/out)
__global__ void __launch_bounds__(512) bp_seed(const float* __restrict__ llr0,
                                               const float* __restrict__ v2c_prev,
                                               float* __restrict__ acc, float scale) {
    int i = blockIdx.x * 512 + threadIdx.x;
    pdl_trigger();
    pdl_wait();   // v2c_prev produced by the preceding check kernel
    float4 l = __ldg(&reinterpret_cast<const float4*>(llr0)[i]);
    float4 p = __ldg(&reinterpret_cast<const float4*>(v2c_prev)[i]);
    float4 s = make_float4(fmaf(scale, l.x, -p.x), fmaf(scale, l.y, -p.y),
                           fmaf(scale, l.z, -p.z), fmaf(scale, l.w, -p.w));
    reinterpret_cast<float4*>(acc)[i] = s;
}

// check-node update: gather src (L2-only), min-sum, scatter-add into pre-seeded
// dst. Entire prologue (mbarrier init, TMA adj fetch + wait, smem index loads)
// runs BEFORE pdl_wait; only the src gathers / dst atomics are gated.
__global__ void __launch_bounds__(CBLK) bp_check(const int* __restrict__ adj,
                                                 const float* __restrict__ gamma_p,
                                                 const float* __restrict__ src,
                                                 float* __restrict__ dst) {
    __shared__ __align__(16) int s_adj[CBLK * DC];
    __shared__ __align__(8) unsigned long long s_mbar;

    const int tid = threadIdx.x;
    uint32_t mbar = smem_u32(&s_mbar);
    uint32_t sdst = smem_u32(s_adj);

    if (tid == 0) {
        asm volatile("mbarrier.init.shared.b64 [%0], 1;" :: "r"(mbar) : "memory");
    }
    __syncthreads();
    if (tid == 0) {
        asm volatile("mbarrier.arrive.expect_tx.shared.b64 _, [%0], %1;"
                     :: "r"(mbar), "r"((uint32_t)ADJ_BYTES) : "memory");
        const int* gsrc = adj + (size_t)blockIdx.x * (CBLK * DC);
        asm volatile(
            "cp.async.bulk.shared::cta.global.mbarrier::complete_tx::bytes "
            "[%0], [%1], %2, [%3];"
            :: "r"(sdst), "l"(gsrc), "r"((uint32_t)ADJ_BYTES), "r"(mbar) : "memory");
    }
    pdl_trigger();
    const float gamma = __ldg(gamma_p);   // kernel input, safe pre-wait

    // wait for TMA completion (phase 0) — input-only dependency, pre-wait
    {
        uint32_t done;
        asm volatile(
            "{\n\t.reg .pred p;\n\t"
            "mbarrier.try_wait.parity.acquire.cta.shared::cta.b64 p, [%1], 0;\n\t"
            "selp.b32 %0, 1, 0, p;\n\t}"
            : "=r"(done) : "r"(mbar) : "memory");
        while (!done) {
            asm volatile(
                "{\n\t.reg .pred p;\n\t"
                "mbarrier.try_wait.parity.acquire.cta.shared::cta.b64 p, [%1], 0, 0x989680;\n\t"
                "selp.b32 %0, 1, 0, p;\n\t}"
                : "=r"(done) : "r"(mbar) : "memory");
        }
    }

    int idx[DC];
    #pragma unroll
    for (int j = 0; j < DC; j++) idx[j] = s_adj[tid * DC + j];

    pdl_wait();   // src and seeded dst produced by the predecessor
    const float vlast = __ldg(&src[N_VAR - 1]);  // all padded (-1) slots wrap here

    float mag = __int_as_float(0x7f800000);  // +inf
    unsigned sgn = 0u;
    #pragma unroll
    for (int j = 0; j < DC; j++) {
        float v = (idx[j] >= 0) ? __ldcg(&src[idx[j]]) : vlast;
        sgn ^= (__float_as_uint(v + 1e-12f) & 0x80000000u);
        mag = fminf(mag, fabsf(v));
    }
    float c2v = __uint_as_float(__float_as_uint(gamma * mag) ^ sgn);

    #pragma unroll
    for (int j = 0; j < DC; j++) {
        if (idx[j] >= 0) atomicAdd(&dst[idx[j]], c2v);
    }
}

template <typename... Args>
static void launch_pdl(void (*kern)(Args...), int grid, int block, Args... args) {
    cudaLaunchConfig_t cfg = {};
    cfg.gridDim = dim3(grid);
    cfg.blockDim = dim3(block);
    cfg.stream = 0;
    cudaLaunchAttribute attr[1];
    attr[0].id = cudaLaunchAttributeProgrammaticStreamSerialization;
    attr[0].val.programmaticStreamSerializationAllowed = 1;
    cfg.attrs = attr;
    cfg.numAttrs = 1;
    cudaLaunchKernelEx(&cfg, kern, args...);
}

extern "C" void kernel_launch(void* const* d_in, const int* in_sizes, int n_in,
                              void* d_out, int out_size) {
    const float* llr0  = (const float*)d_in[0];
    const float* gamma = (const float*)d_in[1];
    const int*   adj   = (const int*)d_in[2];
    float* out = (float*)d_out;

    float *b0, *b1, *b2;
    cudaGetSymbolAddress((void**)&b0, g_b0);
    cudaGetSymbolAddress((void**)&b1, g_b1);
    cudaGetSymbolAddress((void**)&b2, g_b2);

    const int seed_blocks = N_VAR / 4 / 512;   // 2048
    const int chk_blocks = M_CHK / CBLK;       // 16384

    // n_iter = 5. Iter 1 is exact identity (v2c1 = llr0). Remaining 4 rounds:
    // accumulators pre-seeded with (llr0 - v2c_prev) so check's atomics produce
    // v2c_next in place; final accumulator is d_out seeded with (2*llr0 - v2c_4).
    // All launches use PDL; each kernel's input-only prologue overlaps the
    // predecessor's tail wave.
    launch_pdl(bp_zero, seed_blocks, 512, b0);                       // b0 = 0
    launch_pdl(bp_check, chk_blocks, CBLK, adj, gamma, llr0, b0);    // b0 = v2c_2
    launch_pdl(bp_seed, seed_blocks, 512, llr0, (const float*)b0, b1, 1.f); // b1 = llr0 - v2c_2
    launch_pdl(bp_check, chk_blocks, CBLK, adj, gamma, (const float*)b0, b1); // b1 = v2c_3
    launch_pdl(bp_seed, seed_blocks, 512, llr0, (const float*)b1, b2, 1.f); // b2 = llr0 - v2c_3
    launch_pdl(bp_check, chk_blocks, CBLK, adj, gamma, (const float*)b1, b2); // b2 = v2c_4
    launch_pdl(bp_seed, seed_blocks, 512, llr0, (const float*)b2, out, 2.f); // out = 2*llr0 - v2c_4
    launch_pdl(bp_check, chk_blocks, CBLK, adj, gamma, (const float*)b2, out); // out = llr0 + v2c_5
}